// round 3
// baseline (speedup 1.0000x reference)
#include <cuda_runtime.h>
#include <cuda_bf16.h>

#define NPTS   100000
#define GROUPS 12500
#define TPB    256
#define NCTA   152

#define WKV_LD 152
#define QW_LD  136
#define NF_LD  152
#define XA_LD  136
#define Y_LD   132

// smem byte offsets
#define OFF_WKV   0         // 256*152*2 = 77824
#define OFF_QW    77824     // 128*136*2 = 34816
#define OFF_LW    112640    // 34816
#define OFF_NF    147456    // 8*16*152*2 = 38912
#define OFF_XA    186368    // 16*136*2 = 4352
#define OFF_Q     190720    // 8*128*2 = 2048
#define OFF_XF    192768    // 8*128*4 = 4096
#define OFF_X1    196864    // 4096
#define OFF_AF    200960    // 4096
#define OFF_Y     205056    // 8*132*4 = 4224
#define OFF_BIAS  209280    // 1024*4 = 4096
#define SMEM_TOTAL 213376

#define SCALE 0.08838834764831845f   // 1/sqrt(128)

static __device__ __align__(16) __nv_bfloat16 g_wkv[256 * WKV_LD];
static __device__ __align__(16) __nv_bfloat16 g_qwT[128 * QW_LD];
static __device__ __align__(16) __nv_bfloat16 g_lwT[128 * QW_LD];

// ---------------- prep: transpose weights to bf16 [n][k] ----------------
__global__ void prep_kernel(const float* __restrict__ qw, const float* __restrict__ kw,
                            const float* __restrict__ vw, const float* __restrict__ lw) {
    int stride = gridDim.x * blockDim.x;
    for (int i = blockIdx.x * blockDim.x + threadIdx.x; i < 256 * WKV_LD; i += stride) {
        int n = i / WKV_LD, k = i - n * WKV_LD;
        float v = 0.f;
        if (k < 131) v = (n < 128) ? kw[k * 128 + n] : vw[k * 128 + (n - 128)];
        g_wkv[i] = __float2bfloat16_rn(v);
    }
    for (int i = blockIdx.x * blockDim.x + threadIdx.x; i < 128 * QW_LD; i += stride) {
        int n = i / QW_LD, k = i - n * QW_LD;
        g_qwT[i] = __float2bfloat16_rn(k < 128 ? qw[k * 128 + n] : 0.f);
        g_lwT[i] = __float2bfloat16_rn(k < 128 ? lw[k * 128 + n] : 0.f);
    }
}

// ---------------- device helpers ----------------
__device__ __forceinline__ unsigned s2u(const void* p) {
    return (unsigned)__cvta_generic_to_shared(p);
}
__device__ __forceinline__ void ldsm4(unsigned& r0, unsigned& r1, unsigned& r2, unsigned& r3,
                                      unsigned a) {
    asm volatile("ldmatrix.sync.aligned.m8n8.x4.shared.b16 {%0,%1,%2,%3},[%4];"
                 : "=r"(r0), "=r"(r1), "=r"(r2), "=r"(r3) : "r"(a));
}
__device__ __forceinline__ void mma16816(float* c, unsigned a0, unsigned a1, unsigned a2,
                                         unsigned a3, unsigned b0, unsigned b1) {
    asm volatile(
        "mma.sync.aligned.m16n8k16.row.col.f32.bf16.bf16.f32 "
        "{%0,%1,%2,%3},{%4,%5,%6,%7},{%8,%9},{%0,%1,%2,%3};"
        : "+f"(c[0]), "+f"(c[1]), "+f"(c[2]), "+f"(c[3])
        : "r"(a0), "r"(a1), "r"(a2), "r"(a3), "r"(b0), "r"(b1));
}
// A[16 x 152-pad] @ W^T(16 n-rows per np, 9 k-tiles) -> acc[16 ntiles][4]
__device__ __forceinline__ void proj16(float acc[16][4], unsigned aBase, unsigned bBase) {
#pragma unroll
    for (int kt = 0; kt < 9; kt++) {
        unsigned a0, a1, a2, a3;
        ldsm4(a0, a1, a2, a3, aBase + kt * 32);
#pragma unroll
        for (int np = 0; np < 8; np++) {
            unsigned b0, b1, b2, b3;
            ldsm4(b0, b1, b2, b3, bBase + np * (16 * WKV_LD * 2) + kt * 32);
            mma16816(acc[2 * np], a0, a1, a2, a3, b0, b2);
            mma16816(acc[2 * np + 1], a0, a1, a2, a3, b1, b3);
        }
    }
}
// [16x128] @ 16 cols of W^T (2 ntiles), 8 k-tiles
__device__ __forceinline__ void gemm2(float acc[2][4], unsigned aBase, unsigned bBase) {
#pragma unroll
    for (int kt = 0; kt < 8; kt++) {
        unsigned a0, a1, a2, a3, b0, b1, b2, b3;
        ldsm4(a0, a1, a2, a3, aBase + kt * 32);
        ldsm4(b0, b1, b2, b3, bBase + kt * 32);
        mma16816(acc[0], a0, a1, a2, a3, b0, b2);
        mma16816(acc[1], a0, a1, a2, a3, b1, b3);
    }
}
__device__ __forceinline__ float wsum(float v) {
    v += __shfl_xor_sync(~0u, v, 16);
    v += __shfl_xor_sync(~0u, v, 8);
    v += __shfl_xor_sync(~0u, v, 4);
    v += __shfl_xor_sync(~0u, v, 2);
    v += __shfl_xor_sync(~0u, v, 1);
    return v;
}

// ---------------- fused kernel ----------------
__global__ void __launch_bounds__(TPB, 1)
fused_kernel(const float* __restrict__ x, const float* __restrict__ feat,
             const float* __restrict__ xyz,
             const float* __restrict__ qb, const float* __restrict__ kb,
             const float* __restrict__ vb, const float* __restrict__ lb,
             const float* __restrict__ g1, const float* __restrict__ b1,
             const float* __restrict__ g2, const float* __restrict__ b2,
             float* __restrict__ out) {
    extern __shared__ char sm[];
    __nv_bfloat16* s_wkv = (__nv_bfloat16*)(sm + OFF_WKV);
    __nv_bfloat16* s_qw  = (__nv_bfloat16*)(sm + OFF_QW);
    __nv_bfloat16* s_lw  = (__nv_bfloat16*)(sm + OFF_LW);
    __nv_bfloat16* s_nf  = (__nv_bfloat16*)(sm + OFF_NF);
    __nv_bfloat16* s_xa  = (__nv_bfloat16*)(sm + OFF_XA);
    __nv_bfloat16* s_q   = (__nv_bfloat16*)(sm + OFF_Q);
    float* s_xf   = (float*)(sm + OFF_XF);
    float* s_x1   = (float*)(sm + OFF_X1);
    float* s_af   = (float*)(sm + OFF_AF);
    float* s_y    = (float*)(sm + OFF_Y);
    float* s_bias = (float*)(sm + OFF_BIAS);

    const int tid = threadIdx.x;
    const int w = tid >> 5;
    const int lane = tid & 31;

    // weights: device-global -> smem (uint4 copies)
    {
        uint4* d0 = (uint4*)s_wkv; const uint4* src0 = (const uint4*)g_wkv;
        for (int i = tid; i < 256 * WKV_LD / 8; i += TPB) d0[i] = src0[i];
        uint4* d1 = (uint4*)s_qw; const uint4* src1 = (const uint4*)g_qwT;
        for (int i = tid; i < 128 * QW_LD / 8; i += TPB) d1[i] = src1[i];
        uint4* d2 = (uint4*)s_lw; const uint4* src2 = (const uint4*)g_lwT;
        for (int i = tid; i < 128 * QW_LD / 8; i += TPB) d2[i] = src2[i];
    }
    {
        const float* srcs[8] = {qb, kb, vb, lb, g1, b1, g2, b2};
        for (int i = tid; i < 1024; i += TPB) s_bias[i] = srcs[i >> 7][i & 127];
    }
    // zero pads once (rows 8-15 of s_xa; cols >=131 of s_nf)
    for (int i = tid; i < 16 * XA_LD; i += TPB) s_xa[i] = __float2bfloat16(0.f);
    for (int i = tid; i < 8 * 16 * NF_LD; i += TPB) s_nf[i] = __float2bfloat16(0.f);
    __syncthreads();

    const float* s_kbias = s_bias + 128;
    const float* s_vbias = s_bias + 256;
    const float* s_lbias = s_bias + 384;
    const float* s_g1 = s_bias + 512;
    const float* s_b1 = s_bias + 640;
    const float* s_g2 = s_bias + 768;
    const float* s_b2 = s_bias + 896;

    const int tc = (lane & 3) * 2;          // col pair offset in C-frag
    const int h1 = lane >> 4;               // head context of row t/4
    const unsigned aQ  = s2u(s_xa) + (lane & 15) * (XA_LD * 2) + (lane >> 4) * 16;
    const unsigned bQ  = s2u(s_qw) + (w * 16 + (lane & 15)) * (QW_LD * 2) + (lane >> 4) * 16;
    const unsigned bL  = s2u(s_lw) + (w * 16 + (lane & 15)) * (QW_LD * 2) + (lane >> 4) * 16;
    const unsigned aNf = s2u(s_nf + w * 16 * NF_LD) + (lane & 15) * (NF_LD * 2) + (lane >> 4) * 16;
    const unsigned bK  = s2u(s_wkv) + (lane & 15) * (WKV_LD * 2) + (lane >> 4) * 16;
    const unsigned bV  = bK + 128 * (WKV_LD * 2);

    for (int g = blockIdx.x; g < GROUPS; g += gridDim.x) {
        const int n0 = g * 8;
        // ---- load x (warp-own row) ----
        {
            float4 v = ((const float4*)(x + (size_t)(n0 + w) * 128))[lane];
            ((float4*)(s_xf + w * 128))[lane] = v;
            *(__nv_bfloat162*)(s_xa + w * XA_LD + 4 * lane) = __floats2bfloat162_rn(v.x, v.y);
            *(__nv_bfloat162*)(s_xa + w * XA_LD + 4 * lane + 2) = __floats2bfloat162_rn(v.z, v.w);
        }
        // ---- load nf = [feat | xyz] (warp-own 16x131) ----
        {
            const float4* f4 = (const float4*)(feat + (size_t)(n0 + w) * 2048);
            __nv_bfloat16* nf = s_nf + w * 16 * NF_LD;
#pragma unroll
            for (int i = 0; i < 16; i++) {
                float4 v = f4[i * 32 + lane];
                *(__nv_bfloat162*)(nf + i * NF_LD + 4 * lane) = __floats2bfloat162_rn(v.x, v.y);
                *(__nv_bfloat162*)(nf + i * NF_LD + 4 * lane + 2) = __floats2bfloat162_rn(v.z, v.w);
            }
            if (lane < 16) {
                const float* xz = xyz + (size_t)(n0 + w) * 48 + lane * 3;
                nf[lane * NF_LD + 128] = __float2bfloat16_rn(xz[0]);
                nf[lane * NF_LD + 129] = __float2bfloat16_rn(xz[1]);
                nf[lane * NF_LD + 130] = __float2bfloat16_rn(xz[2]);
            }
        }
        __syncthreads();

        // ---- Q gemm: warp w -> cols [16w,16w+16) for the 8 points ----
        {
            float acc[2][4] = {};
            gemm2(acc, aQ, bQ);
            int r = lane >> 2;
#pragma unroll
            for (int nt = 0; nt < 2; nt++) {
                int c = w * 16 + nt * 8 + tc;
                *(__nv_bfloat162*)(s_q + r * 128 + c) =
                    __floats2bfloat162_rn(acc[nt][0] + s_bias[c], acc[nt][1] + s_bias[c + 1]);
            }
        }
        // ---- K projection (regs) ----
        float accK[16][4] = {};
        proj16(accK, aNf, bK);
#pragma unroll
        for (int nt = 0; nt < 16; nt++) {
            float kb0 = s_kbias[nt * 8 + tc], kb1 = s_kbias[nt * 8 + tc + 1];
            accK[nt][0] += kb0; accK[nt][1] += kb1;
            accK[nt][2] += kb0; accK[nt][3] += kb1;
        }
        __syncthreads();   // s_q ready

        // ---- attention scores from accK + s_q ----
        float qv1[8], qv2[8];
#pragma unroll
        for (int m = 0; m < 4; m++)
#pragma unroll
            for (int b = 0; b < 2; b++) {
                int d = 8 * m + tc + b;
                qv1[2 * m + b] = __bfloat162float(s_q[w * 128 + h1 * 32 + d]);
                qv2[2 * m + b] = __bfloat162float(s_q[w * 128 + (h1 + 2) * 32 + d]);
            }
        float sc1[4], sc2[4];
#pragma unroll
        for (int cb = 0; cb < 4; cb++) {
            float a = 0.f, b = 0.f;
#pragma unroll
            for (int m = 0; m < 4; m++) {
                int nt = 4 * cb + m;
                a += accK[nt][0] * qv1[2 * m] + accK[nt][1] * qv1[2 * m + 1];
                b += accK[nt][2] * qv2[2 * m] + accK[nt][3] * qv2[2 * m + 1];
            }
            a += __shfl_xor_sync(~0u, a, 1); a += __shfl_xor_sync(~0u, a, 2);
            b += __shfl_xor_sync(~0u, b, 1); b += __shfl_xor_sync(~0u, b, 2);
            sc1[cb] = a * SCALE; sc2[cb] = b * SCALE;
        }
        // softmax over kk (local cb + butterfly 4,8 across kkhi)
        float m1 = fmaxf(fmaxf(sc1[0], sc1[1]), fmaxf(sc1[2], sc1[3]));
        float m2 = fmaxf(fmaxf(sc2[0], sc2[1]), fmaxf(sc2[2], sc2[3]));
        m1 = fmaxf(m1, __shfl_xor_sync(~0u, m1, 4)); m1 = fmaxf(m1, __shfl_xor_sync(~0u, m1, 8));
        m2 = fmaxf(m2, __shfl_xor_sync(~0u, m2, 4)); m2 = fmaxf(m2, __shfl_xor_sync(~0u, m2, 8));
        float e1[4], e2[4], sum1 = 0.f, sum2 = 0.f;
#pragma unroll
        for (int cb = 0; cb < 4; cb++) {
            e1[cb] = __expf(sc1[cb] - m1); sum1 += e1[cb];
            e2[cb] = __expf(sc2[cb] - m2); sum2 += e2[cb];
        }
        sum1 += __shfl_xor_sync(~0u, sum1, 4); sum1 += __shfl_xor_sync(~0u, sum1, 8);
        sum2 += __shfl_xor_sync(~0u, sum2, 4); sum2 += __shfl_xor_sync(~0u, sum2, 8);
        float inv1 = 1.f / sum1, inv2 = 1.f / sum2;

        // ---- V projection + att_feat ----
        float accV[16][4] = {};
        proj16(accV, aNf, bV);
        float af1[8] = {}, af2[8] = {};
#pragma unroll
        for (int nt = 0; nt < 16; nt++) {
            float vb0 = s_vbias[nt * 8 + tc], vb1 = s_vbias[nt * 8 + tc + 1];
            float p1 = e1[nt >> 2] * inv1, p2 = e2[nt >> 2] * inv2;
            int m = nt & 3;
            af1[2 * m]     += p1 * (accV[nt][0] + vb0);
            af1[2 * m + 1] += p1 * (accV[nt][1] + vb1);
            af2[2 * m]     += p2 * (accV[nt][2] + vb0);
            af2[2 * m + 1] += p2 * (accV[nt][3] + vb1);
        }
#pragma unroll
        for (int i = 0; i < 8; i++) {
            af1[i] += __shfl_xor_sync(~0u, af1[i], 4);
            af1[i] += __shfl_xor_sync(~0u, af1[i], 8);
            af2[i] += __shfl_xor_sync(~0u, af2[i], 4);
            af2[i] += __shfl_xor_sync(~0u, af2[i], 8);
        }
        if (((lane >> 2) & 3) == 0) {
#pragma unroll
            for (int m = 0; m < 4; m++)
#pragma unroll
                for (int b = 0; b < 2; b++) {
                    int d = 8 * m + tc + b;
                    s_af[w * 128 + h1 * 32 + d] = af1[2 * m + b];
                    s_af[w * 128 + (h1 + 2) * 32 + d] = af2[2 * m + b];
                }
        }
        __syncwarp();

        // ---- x1 = LN1(x + att_feat) ----
        {
            float v[4];
#pragma unroll
            for (int i = 0; i < 4; i++)
                v[i] = s_xf[w * 128 + 4 * lane + i] + s_af[w * 128 + 4 * lane + i];
            float mean = wsum(v[0] + v[1] + v[2] + v[3]) * (1.f / 128.f);
            float vs = 0.f;
#pragma unroll
            for (int i = 0; i < 4; i++) { float d = v[i] - mean; vs += d * d; }
            float var = wsum(vs) * (1.f / 128.f);
            float rs = rsqrtf(var + 1e-5f);
#pragma unroll
            for (int i = 0; i < 4; i++) {
                int c = 4 * lane + i;
                v[i] = (v[i] - mean) * rs * s_g1[c] + s_b1[c];
                s_x1[w * 128 + c] = v[i];
            }
            *(__nv_bfloat162*)(s_xa + w * XA_LD + 4 * lane) = __floats2bfloat162_rn(v[0], v[1]);
            *(__nv_bfloat162*)(s_xa + w * XA_LD + 4 * lane + 2) = __floats2bfloat162_rn(v[2], v[3]);
        }
        __syncthreads();

        // ---- linear layer + residual ----
        {
            float acc[2][4] = {};
            gemm2(acc, aQ, bL);
            int r = lane >> 2;
#pragma unroll
            for (int nt = 0; nt < 2; nt++) {
                int c = w * 16 + nt * 8 + tc;
                s_y[r * Y_LD + c]     = s_x1[r * 128 + c] + acc[nt][0] + s_lbias[c];
                s_y[r * Y_LD + c + 1] = s_x1[r * 128 + c + 1] + acc[nt][1] + s_lbias[c + 1];
            }
        }
        __syncthreads();

        // ---- LN2 + store ----
        {
            float v[4];
#pragma unroll
            for (int i = 0; i < 4; i++) v[i] = s_y[w * Y_LD + 4 * lane + i];
            float mean = wsum(v[0] + v[1] + v[2] + v[3]) * (1.f / 128.f);
            float vs = 0.f;
#pragma unroll
            for (int i = 0; i < 4; i++) { float d = v[i] - mean; vs += d * d; }
            float rs = rsqrtf(wsum(vs) * (1.f / 128.f) + 1e-5f);
            float4 o;
            int c = 4 * lane;
            o.x = (v[0] - mean) * rs * s_g2[c] + s_b2[c];
            o.y = (v[1] - mean) * rs * s_g2[c + 1] + s_b2[c + 1];
            o.z = (v[2] - mean) * rs * s_g2[c + 2] + s_b2[c + 2];
            o.w = (v[3] - mean) * rs * s_g2[c + 3] + s_b2[c + 3];
            ((float4*)(out + (size_t)(n0 + w) * 128))[lane] = o;
        }
    }
}

// ---------------- launch ----------------
extern "C" void kernel_launch(void* const* d_in, const int* in_sizes, int n_in,
                              void* d_out, int out_size) {
    const float* x    = (const float*)d_in[0];
    const float* feat = (const float*)d_in[1];
    const float* xyz  = (const float*)d_in[2];
    const float* qw   = (const float*)d_in[3];
    const float* qb   = (const float*)d_in[4];
    const float* kw   = (const float*)d_in[5];
    const float* kb   = (const float*)d_in[6];
    const float* vw   = (const float*)d_in[7];
    const float* vb   = (const float*)d_in[8];
    const float* lw   = (const float*)d_in[9];
    const float* lb   = (const float*)d_in[10];
    const float* g1   = (const float*)d_in[11];
    const float* b1   = (const float*)d_in[12];
    const float* g2   = (const float*)d_in[13];
    const float* b2   = (const float*)d_in[14];
    float* out = (float*)d_out;

    cudaFuncSetAttribute(fused_kernel, cudaFuncAttributeMaxDynamicSharedMemorySize, SMEM_TOTAL);
    prep_kernel<<<128, 256>>>(qw, kw, vw, lw);
    fused_kernel<<<NCTA, TPB, SMEM_TOTAL>>>(x, feat, xyz, qb, kb, vb, lb, g1, b1, g2, b2, out);
}